// round 1
// baseline (speedup 1.0000x reference)
#include <cuda_runtime.h>
#include <cuda_bf16.h>
#include <cfloat>

// Problem constants
#define BATCH 4
#define TSEQ  2048
#define CDIM  1024
#define NHEAD 16
#define HD    64

// Scratch (device globals; no allocations allowed)
__device__ float g_qkv[(size_t)BATCH * TSEQ * 3 * CDIM]; // 96 MB
__device__ float g_y  [(size_t)BATCH * TSEQ * CDIM];     // 32 MB

// ---------------------------------------------------------------------------
// SGEMM: C[M,N] = A[M,K] @ B[N,K]^T + bias[N]
// Block tile 128x128, K-step 8, 256 threads, 8x8 per-thread register tile.
// Assumes M%128==0, N%128==0, K%8==0 (true for all calls here).
// ---------------------------------------------------------------------------
__global__ __launch_bounds__(256, 2)
void sgemm_bias(const float* __restrict__ A, const float* __restrict__ B,
                const float* __restrict__ bias, float* __restrict__ C,
                int M, int N, int K)
{
    __shared__ float As[8][128];
    __shared__ float Bs[8][128];

    const int tid = threadIdx.x;
    const int tx  = tid & 15;   // 0..15 -> N direction
    const int ty  = tid >> 4;   // 0..15 -> M direction
    const int m0  = blockIdx.y * 128;
    const int n0  = blockIdx.x * 128;

    const int arow = tid >> 1;        // 0..127
    const int acol = (tid & 1) * 4;   // 0 or 4

    const float* Aptr = A + (size_t)(m0 + arow) * K + acol;
    const float* Bptr = B + (size_t)(n0 + arow) * K + acol;

    float acc[8][8];
#pragma unroll
    for (int i = 0; i < 8; i++)
#pragma unroll
        for (int j = 0; j < 8; j++) acc[i][j] = 0.0f;

    for (int k0 = 0; k0 < K; k0 += 8) {
        float4 av = *(const float4*)(Aptr + k0);
        float4 bv = *(const float4*)(Bptr + k0);
        __syncthreads();
        As[acol + 0][arow] = av.x;
        As[acol + 1][arow] = av.y;
        As[acol + 2][arow] = av.z;
        As[acol + 3][arow] = av.w;
        Bs[acol + 0][arow] = bv.x;
        Bs[acol + 1][arow] = bv.y;
        Bs[acol + 2][arow] = bv.z;
        Bs[acol + 3][arow] = bv.w;
        __syncthreads();

#pragma unroll
        for (int kk = 0; kk < 8; kk++) {
            float4 a0 = *(const float4*)&As[kk][ty * 8];
            float4 a1 = *(const float4*)&As[kk][ty * 8 + 4];
            float4 b0 = *(const float4*)&Bs[kk][tx * 8];
            float4 b1 = *(const float4*)&Bs[kk][tx * 8 + 4];
            float a[8] = {a0.x, a0.y, a0.z, a0.w, a1.x, a1.y, a1.z, a1.w};
            float b[8] = {b0.x, b0.y, b0.z, b0.w, b1.x, b1.y, b1.z, b1.w};
#pragma unroll
            for (int i = 0; i < 8; i++)
#pragma unroll
                for (int j = 0; j < 8; j++)
                    acc[i][j] = fmaf(a[i], b[j], acc[i][j]);
        }
    }

    // epilogue with bias
#pragma unroll
    for (int i = 0; i < 8; i++) {
        const int row = m0 + ty * 8 + i;
        float* crow = C + (size_t)row * N + n0 + tx * 8;
        const float* brow = bias + n0 + tx * 8;
        float4 o0, o1;
        o0.x = acc[i][0] + brow[0];
        o0.y = acc[i][1] + brow[1];
        o0.z = acc[i][2] + brow[2];
        o0.w = acc[i][3] + brow[3];
        o1.x = acc[i][4] + brow[4];
        o1.y = acc[i][5] + brow[5];
        o1.z = acc[i][6] + brow[6];
        o1.w = acc[i][7] + brow[7];
        *(float4*)(crow)     = o0;
        *(float4*)(crow + 4) = o1;
    }
}

// ---------------------------------------------------------------------------
// Flash attention (causal), fp32. One block = one (b, h, 64-row q-tile).
// 256 threads as 16x16; per-thread 4x4 tiles for S and O.
// Shared: Qst[64][65] (d-major), Kst[64][65] (d-major), Pst[64][65] (c-major),
//         Vs[64][64] (k-major). Total 66304 B dynamic smem.
// ---------------------------------------------------------------------------
__global__ __launch_bounds__(256, 2)
void attn_flash(const float* __restrict__ qkv, float* __restrict__ y)
{
    extern __shared__ float sm[];
    float* Qst = sm;                // [64][65], Qst[d][r]
    float* Kst = Qst + 64 * 65;    // [64][65], Kst[d][c]
    float* Pst = Kst + 64 * 65;    // [64][65], Pst[c][r]
    float* Vs  = Pst + 64 * 65;    // [64][64], Vs[k][d]

    const int qtile = blockIdx.x;       // 0..31
    const int bh    = blockIdx.y;       // 0..63
    const int b = bh >> 4;
    const int h = bh & 15;

    const float* qbase = qkv + (size_t)b * TSEQ * 3 * CDIM + h * HD;
    const float* kbase = qbase + CDIM;
    const float* vbase = qbase + 2 * CDIM;

    const int tid = threadIdx.x;
    const int tx = tid & 15;   // column group (key idx / d idx)
    const int ty = tid >> 4;   // row group (query idx)
    const int q0 = qtile * 64;

    // Load Q tile: 64 rows x 64 d, transposed into Qst[d][r]
    for (int it = tid; it < 64 * 16; it += 256) {
        const int r  = it >> 4;
        const int c4 = (it & 15) * 4;
        float4 v = *(const float4*)(qbase + (size_t)(q0 + r) * (3 * CDIM) + c4);
        Qst[(c4 + 0) * 65 + r] = v.x;
        Qst[(c4 + 1) * 65 + r] = v.y;
        Qst[(c4 + 2) * 65 + r] = v.z;
        Qst[(c4 + 3) * 65 + r] = v.w;
    }

    float m_i[4], l_i[4], o[4][4];
#pragma unroll
    for (int i = 0; i < 4; i++) {
        m_i[i] = -1e30f;
        l_i[i] = 0.0f;
#pragma unroll
        for (int j = 0; j < 4; j++) o[i][j] = 0.0f;
    }

    const int ntiles = qtile + 1;   // causal: only k-tiles with j0 <= q0
    const float scale = 0.125f;     // 1/sqrt(64)

    for (int jt = 0; jt < ntiles; jt++) {
        const int j0 = jt * 64;
        __syncthreads();
        // Load K (transposed) and V (natural)
        for (int it = tid; it < 64 * 16; it += 256) {
            const int r  = it >> 4;
            const int c4 = (it & 15) * 4;
            float4 kv = *(const float4*)(kbase + (size_t)(j0 + r) * (3 * CDIM) + c4);
            Kst[(c4 + 0) * 65 + r] = kv.x;
            Kst[(c4 + 1) * 65 + r] = kv.y;
            Kst[(c4 + 2) * 65 + r] = kv.z;
            Kst[(c4 + 3) * 65 + r] = kv.w;
            float4 vv = *(const float4*)(vbase + (size_t)(j0 + r) * (3 * CDIM) + c4);
            *(float4*)(Vs + r * 64 + c4) = vv;
        }
        __syncthreads();

        // S = Q @ K^T (per-thread 4x4)
        float s[4][4];
#pragma unroll
        for (int i = 0; i < 4; i++)
#pragma unroll
            for (int j = 0; j < 4; j++) s[i][j] = 0.0f;

#pragma unroll 4
        for (int d = 0; d < 64; d++) {
            float qr[4], kc[4];
#pragma unroll
            for (int i = 0; i < 4; i++) qr[i] = Qst[d * 65 + ty * 4 + i];
#pragma unroll
            for (int j = 0; j < 4; j++) kc[j] = Kst[d * 65 + tx * 4 + j];
#pragma unroll
            for (int i = 0; i < 4; i++)
#pragma unroll
                for (int j = 0; j < 4; j++)
                    s[i][j] = fmaf(qr[i], kc[j], s[i][j]);
        }

        // scale + causal mask
#pragma unroll
        for (int i = 0; i < 4; i++) {
            const int qi = q0 + ty * 4 + i;
#pragma unroll
            for (int j = 0; j < 4; j++) {
                const int kj = j0 + tx * 4 + j;
                s[i][j] = (kj <= qi) ? s[i][j] * scale : -1e30f;
            }
        }

        // online softmax update per row
#pragma unroll
        for (int i = 0; i < 4; i++) {
            float mx = fmaxf(fmaxf(s[i][0], s[i][1]), fmaxf(s[i][2], s[i][3]));
#pragma unroll
            for (int off = 1; off < 16; off <<= 1)
                mx = fmaxf(mx, __shfl_xor_sync(0xffffffffu, mx, off));
            const float mnew  = fmaxf(m_i[i], mx);
            const float alpha = __expf(m_i[i] - mnew);
            float rs = 0.0f;
#pragma unroll
            for (int j = 0; j < 4; j++) {
                const float p = __expf(s[i][j] - mnew);
                s[i][j] = p;
                rs += p;
            }
#pragma unroll
            for (int off = 1; off < 16; off <<= 1)
                rs += __shfl_xor_sync(0xffffffffu, rs, off);
            l_i[i] = l_i[i] * alpha + rs;
            m_i[i] = mnew;
#pragma unroll
            for (int j = 0; j < 4; j++) o[i][j] *= alpha;
            // write P transposed: Pst[c][r]
#pragma unroll
            for (int j = 0; j < 4; j++)
                Pst[(tx * 4 + j) * 65 + (ty * 4 + i)] = s[i][j];
        }
        __syncthreads();

        // O += P @ V  (outer product over key dim)
#pragma unroll 4
        for (int kk = 0; kk < 64; kk++) {
            float pr[4], vc[4];
#pragma unroll
            for (int i = 0; i < 4; i++) pr[i] = Pst[kk * 65 + ty * 4 + i];
#pragma unroll
            for (int j = 0; j < 4; j++) vc[j] = Vs[kk * 64 + tx * 4 + j];
#pragma unroll
            for (int i = 0; i < 4; i++)
#pragma unroll
                for (int j = 0; j < 4; j++)
                    o[i][j] = fmaf(pr[i], vc[j], o[i][j]);
        }
    }

    // epilogue: normalize and write y[b][t][h*64 + d]
#pragma unroll
    for (int i = 0; i < 4; i++) {
        const float inv = 1.0f / l_i[i];
        const int t = q0 + ty * 4 + i;
        float* dst = y + (size_t)b * TSEQ * CDIM + (size_t)t * CDIM + h * HD + tx * 4;
        float4 ov;
        ov.x = o[i][0] * inv;
        ov.y = o[i][1] * inv;
        ov.z = o[i][2] * inv;
        ov.w = o[i][3] * inv;
        *(float4*)dst = ov;
    }
}

// ---------------------------------------------------------------------------
extern "C" void kernel_launch(void* const* d_in, const int* in_sizes, int n_in,
                              void* d_out, int out_size)
{
    (void)in_sizes; (void)n_in; (void)out_size;
    const float* x      = (const float*)d_in[0];
    const float* w_attn = (const float*)d_in[1];
    const float* b_attn = (const float*)d_in[2];
    const float* w_proj = (const float*)d_in[3];
    const float* b_proj = (const float*)d_in[4];
    float* out = (float*)d_out;

    float* qkv = nullptr;
    float* y   = nullptr;
    cudaGetSymbolAddress((void**)&qkv, g_qkv);
    cudaGetSymbolAddress((void**)&y,   g_y);

    const int M = BATCH * TSEQ;   // 8192

    // 1) QKV projection: [8192,1024] @ [3072,1024]^T + b
    sgemm_bias<<<dim3(3 * CDIM / 128, M / 128), 256>>>(x, w_attn, b_attn, qkv,
                                                       M, 3 * CDIM, CDIM);

    // 2) causal flash attention
    const size_t smem = (size_t)(3 * 65 + 64) * 64 * sizeof(float); // 66304 B
    static bool attr_set = false; // idempotent attribute set (not a stream op)
    cudaFuncSetAttribute(attn_flash, cudaFuncAttributeMaxDynamicSharedMemorySize,
                         (int)smem);
    (void)attr_set;
    attn_flash<<<dim3(TSEQ / 64, BATCH * NHEAD), 256, smem>>>(qkv, y);

    // 3) output projection: [8192,1024] @ [1024,1024]^T + b
    sgemm_bias<<<dim3(CDIM / 128, M / 128), 256>>>(y, w_proj, b_proj, out,
                                                   M, CDIM, CDIM);
}

// round 2
// speedup vs baseline: 3.0126x; 3.0126x over previous
#include <cuda_runtime.h>
#include <cuda_bf16.h>
#include <cfloat>

// Problem constants
#define BATCH 4
#define TSEQ  2048
#define CDIM  1024
#define NHEAD 16
#define HD    64

// Scratch (device globals; no allocations allowed)
__device__ float g_qkv[(size_t)BATCH * TSEQ * 3 * CDIM]; // 96 MB
__device__ float g_y  [(size_t)BATCH * TSEQ * CDIM];     // 32 MB

// ---------------------------------------------------------------------------
// tf32 helpers
// ---------------------------------------------------------------------------
__device__ __forceinline__ unsigned f2tf32(float f) {
    unsigned u;
    asm("cvt.rna.tf32.f32 %0, %1;" : "=r"(u) : "f"(f));
    return u;
}

__device__ __forceinline__ void mma_tf32(float c[4],
                                         unsigned a0, unsigned a1, unsigned a2, unsigned a3,
                                         unsigned b0, unsigned b1)
{
    asm volatile(
        "mma.sync.aligned.m16n8k8.row.col.f32.tf32.tf32.f32 "
        "{%0,%1,%2,%3}, {%4,%5,%6,%7}, {%8,%9}, {%0,%1,%2,%3};"
        : "+f"(c[0]), "+f"(c[1]), "+f"(c[2]), "+f"(c[3])
        : "r"(a0), "r"(a1), "r"(a2), "r"(a3), "r"(b0), "r"(b1));
}

// ---------------------------------------------------------------------------
// tf32 GEMM: C[M,N] = A[M,K] @ B[N,K]^T + bias[N]
// Block tile 128x128, K-step 16, 256 threads (8 warps as 2Mx4N),
// warp tile 64x32 = 4x4 m16n8k8 mma tiles. Double-buffered smem.
// Assumes M%128==0, N%128==0, K%16==0.
// ---------------------------------------------------------------------------
#define GPAD 20   // smem row pitch in words for 16-k rows (conflict-free frags)

__global__ __launch_bounds__(256, 2)
void gemm_tf32(const float* __restrict__ A, const float* __restrict__ B,
               const float* __restrict__ bias, float* __restrict__ C,
               int M, int N, int K)
{
    __shared__ unsigned As[2][128 * GPAD];
    __shared__ unsigned Bs[2][128 * GPAD];

    const int tid  = threadIdx.x;
    const int warp = tid >> 5;
    const int lane = tid & 31;
    const int g    = lane >> 2;   // groupID 0..7
    const int t    = lane & 3;    // threadID_in_group 0..3
    const int wm   = warp & 1;    // 0..1  -> M
    const int wn   = warp >> 1;   // 0..3  -> N

    const int m0 = blockIdx.y * 128;
    const int n0 = blockIdx.x * 128;

    // gmem load mapping: 128 rows x 16 k per stage; 512 float4, 256 threads x2
    const int lrow = tid >> 2;         // 0..63 (and +64)
    const int lc4  = (tid & 3) * 4;    // 0,4,8,12

    const float* Ap0 = A + (size_t)(m0 + lrow) * K + lc4;
    const float* Ap1 = A + (size_t)(m0 + lrow + 64) * K + lc4;
    const float* Bp0 = B + (size_t)(n0 + lrow) * K + lc4;
    const float* Bp1 = B + (size_t)(n0 + lrow + 64) * K + lc4;

    float acc[4][4][4];
#pragma unroll
    for (int i = 0; i < 4; i++)
#pragma unroll
        for (int j = 0; j < 4; j++)
#pragma unroll
            for (int c = 0; c < 4; c++) acc[i][j][c] = 0.0f;

    float4 av0, av1, bv0, bv1;

    // preload stage 0
    av0 = *(const float4*)(Ap0);
    av1 = *(const float4*)(Ap1);
    bv0 = *(const float4*)(Bp0);
    bv1 = *(const float4*)(Bp1);
    {
        unsigned* as = As[0];
        unsigned* bs = Bs[0];
        as[(lrow     ) * GPAD + lc4 + 0] = f2tf32(av0.x);
        as[(lrow     ) * GPAD + lc4 + 1] = f2tf32(av0.y);
        as[(lrow     ) * GPAD + lc4 + 2] = f2tf32(av0.z);
        as[(lrow     ) * GPAD + lc4 + 3] = f2tf32(av0.w);
        as[(lrow + 64) * GPAD + lc4 + 0] = f2tf32(av1.x);
        as[(lrow + 64) * GPAD + lc4 + 1] = f2tf32(av1.y);
        as[(lrow + 64) * GPAD + lc4 + 2] = f2tf32(av1.z);
        as[(lrow + 64) * GPAD + lc4 + 3] = f2tf32(av1.w);
        bs[(lrow     ) * GPAD + lc4 + 0] = f2tf32(bv0.x);
        bs[(lrow     ) * GPAD + lc4 + 1] = f2tf32(bv0.y);
        bs[(lrow     ) * GPAD + lc4 + 2] = f2tf32(bv0.z);
        bs[(lrow     ) * GPAD + lc4 + 3] = f2tf32(bv0.w);
        bs[(lrow + 64) * GPAD + lc4 + 0] = f2tf32(bv1.x);
        bs[(lrow + 64) * GPAD + lc4 + 1] = f2tf32(bv1.y);
        bs[(lrow + 64) * GPAD + lc4 + 2] = f2tf32(bv1.z);
        bs[(lrow + 64) * GPAD + lc4 + 3] = f2tf32(bv1.w);
    }
    __syncthreads();

    const int nk = K / 16;
    for (int ks = 0; ks < nk; ks++) {
        const int buf = ks & 1;

        // prefetch next stage gmem -> regs
        if (ks + 1 < nk) {
            const int koff = (ks + 1) * 16;
            av0 = *(const float4*)(Ap0 + koff);
            av1 = *(const float4*)(Ap1 + koff);
            bv0 = *(const float4*)(Bp0 + koff);
            bv1 = *(const float4*)(Bp1 + koff);
        }

        // compute on current buffer: two k8 chunks
        const unsigned* as = As[buf];
        const unsigned* bs = Bs[buf];
#pragma unroll
        for (int kk = 0; kk < 16; kk += 8) {
            unsigned af[4][4], bf[4][2];
#pragma unroll
            for (int im = 0; im < 4; im++) {
                const int mb = wm * 64 + im * 16;
                af[im][0] = as[(mb + g    ) * GPAD + kk + t];
                af[im][1] = as[(mb + g + 8) * GPAD + kk + t];
                af[im][2] = as[(mb + g    ) * GPAD + kk + t + 4];
                af[im][3] = as[(mb + g + 8) * GPAD + kk + t + 4];
            }
#pragma unroll
            for (int jn = 0; jn < 4; jn++) {
                const int nb = wn * 32 + jn * 8;
                bf[jn][0] = bs[(nb + g) * GPAD + kk + t];
                bf[jn][1] = bs[(nb + g) * GPAD + kk + t + 4];
            }
#pragma unroll
            for (int im = 0; im < 4; im++)
#pragma unroll
                for (int jn = 0; jn < 4; jn++)
                    mma_tf32(acc[im][jn],
                             af[im][0], af[im][1], af[im][2], af[im][3],
                             bf[jn][0], bf[jn][1]);
        }

        // store prefetched regs into other buffer
        if (ks + 1 < nk) {
            unsigned* asn = As[buf ^ 1];
            unsigned* bsn = Bs[buf ^ 1];
            asn[(lrow     ) * GPAD + lc4 + 0] = f2tf32(av0.x);
            asn[(lrow     ) * GPAD + lc4 + 1] = f2tf32(av0.y);
            asn[(lrow     ) * GPAD + lc4 + 2] = f2tf32(av0.z);
            asn[(lrow     ) * GPAD + lc4 + 3] = f2tf32(av0.w);
            asn[(lrow + 64) * GPAD + lc4 + 0] = f2tf32(av1.x);
            asn[(lrow + 64) * GPAD + lc4 + 1] = f2tf32(av1.y);
            asn[(lrow + 64) * GPAD + lc4 + 2] = f2tf32(av1.z);
            asn[(lrow + 64) * GPAD + lc4 + 3] = f2tf32(av1.w);
            bsn[(lrow     ) * GPAD + lc4 + 0] = f2tf32(bv0.x);
            bsn[(lrow     ) * GPAD + lc4 + 1] = f2tf32(bv0.y);
            bsn[(lrow     ) * GPAD + lc4 + 2] = f2tf32(bv0.z);
            bsn[(lrow     ) * GPAD + lc4 + 3] = f2tf32(bv0.w);
            bsn[(lrow + 64) * GPAD + lc4 + 0] = f2tf32(bv1.x);
            bsn[(lrow + 64) * GPAD + lc4 + 1] = f2tf32(bv1.y);
            bsn[(lrow + 64) * GPAD + lc4 + 2] = f2tf32(bv1.z);
            bsn[(lrow + 64) * GPAD + lc4 + 3] = f2tf32(bv1.w);
        }
        __syncthreads();
    }

    // epilogue with bias
#pragma unroll
    for (int im = 0; im < 4; im++) {
#pragma unroll
        for (int jn = 0; jn < 4; jn++) {
            const int row = m0 + wm * 64 + im * 16 + g;
            const int col = n0 + wn * 32 + jn * 8 + 2 * t;
            const float b0 = bias[col];
            const float b1 = bias[col + 1];
            float2 v0, v1;
            v0.x = acc[im][jn][0] + b0;
            v0.y = acc[im][jn][1] + b1;
            v1.x = acc[im][jn][2] + b0;
            v1.y = acc[im][jn][3] + b1;
            *(float2*)(C + (size_t)row * N + col)       = v0;
            *(float2*)(C + (size_t)(row + 8) * N + col) = v1;
        }
    }
}

// ---------------------------------------------------------------------------
// Flash attention (causal) with tf32 mma.
// Block = (b, h, 64-row q-tile); 128 threads = 4 warps; each warp owns 16 q rows.
// Tiles of 64 keys. S = Q K^T and O += P V both on tensor pipe.
// Smem (words): Qs[64][68], Ks[64][68], Vs[64][72], Ps[64][68]  => 70656 B
// ---------------------------------------------------------------------------
#define QPAD 68
#define VPAD 72

__global__ __launch_bounds__(128, 2)
void attn_flash_mma(const float* __restrict__ qkv, float* __restrict__ y)
{
    extern __shared__ unsigned smu[];
    unsigned* Qs = smu;                 // [64][QPAD]  row=q, col=d
    unsigned* Ks = Qs + 64 * QPAD;      // [64][QPAD]  row=key, col=d
    unsigned* Vs = Ks + 64 * QPAD;      // [64][VPAD]  row=key, col=d
    unsigned* Ps = Vs + 64 * VPAD;      // [64][QPAD]  row=q, col=key

    const int qtile = blockIdx.x;   // 0..31
    const int bh    = blockIdx.y;   // 0..63
    const int b = bh >> 4;
    const int h = bh & 15;

    const float* qbase = qkv + (size_t)b * TSEQ * 3 * CDIM + h * HD;
    const float* kbase = qbase + CDIM;
    const float* vbase = qbase + 2 * CDIM;

    const int tid  = threadIdx.x;
    const int warp = tid >> 5;
    const int lane = tid & 31;
    const int g    = lane >> 2;
    const int t    = lane & 3;
    const int q0   = qtile * 64;
    const int w16  = warp * 16;

    // Load Q tile (64x64) -> tf32 smem
    for (int idx = tid; idx < 64 * 16; idx += 128) {
        const int r  = idx >> 4;
        const int c4 = (idx & 15) * 4;
        float4 v = *(const float4*)(qbase + (size_t)(q0 + r) * (3 * CDIM) + c4);
        unsigned* p = Qs + r * QPAD + c4;
        p[0] = f2tf32(v.x); p[1] = f2tf32(v.y);
        p[2] = f2tf32(v.z); p[3] = f2tf32(v.w);
    }

    float m_i[2], l_i[2], o[8][4];
#pragma unroll
    for (int rr = 0; rr < 2; rr++) { m_i[rr] = -1e30f; l_i[rr] = 0.0f; }
#pragma unroll
    for (int jn = 0; jn < 8; jn++)
#pragma unroll
        for (int c = 0; c < 4; c++) o[jn][c] = 0.0f;

    const int ntiles = qtile + 1;
    const float scale = 0.125f;   // 1/sqrt(64)

    for (int jt = 0; jt < ntiles; jt++) {
        const int j0 = jt * 64;
        __syncthreads();
        // Load K and V tiles (64x64 each) -> tf32 smem
        for (int idx = tid; idx < 64 * 16; idx += 128) {
            const int r  = idx >> 4;
            const int c4 = (idx & 15) * 4;
            float4 kv = *(const float4*)(kbase + (size_t)(j0 + r) * (3 * CDIM) + c4);
            unsigned* kp = Ks + r * QPAD + c4;
            kp[0] = f2tf32(kv.x); kp[1] = f2tf32(kv.y);
            kp[2] = f2tf32(kv.z); kp[3] = f2tf32(kv.w);
            float4 vv = *(const float4*)(vbase + (size_t)(j0 + r) * (3 * CDIM) + c4);
            unsigned* vp = Vs + r * VPAD + c4;
            vp[0] = f2tf32(vv.x); vp[1] = f2tf32(vv.y);
            vp[2] = f2tf32(vv.z); vp[3] = f2tf32(vv.w);
        }
        __syncthreads();

        // ---- S = Q @ K^T  (warp: 16 q rows x 64 keys) ----
        float s[8][4];
#pragma unroll
        for (int jn = 0; jn < 8; jn++)
#pragma unroll
            for (int c = 0; c < 4; c++) s[jn][c] = 0.0f;

#pragma unroll
        for (int kc = 0; kc < 64; kc += 8) {
            unsigned a0 = Qs[(w16 + g    ) * QPAD + kc + t];
            unsigned a1 = Qs[(w16 + g + 8) * QPAD + kc + t];
            unsigned a2 = Qs[(w16 + g    ) * QPAD + kc + t + 4];
            unsigned a3 = Qs[(w16 + g + 8) * QPAD + kc + t + 4];
#pragma unroll
            for (int jn = 0; jn < 8; jn++) {
                unsigned b0 = Ks[(jn * 8 + g) * QPAD + kc + t];
                unsigned b1 = Ks[(jn * 8 + g) * QPAD + kc + t + 4];
                mma_tf32(s[jn], a0, a1, a2, a3, b0, b1);
            }
        }

        // ---- online softmax (2 rows per thread: g and g+8) ----
#pragma unroll
        for (int rr = 0; rr < 2; rr++) {
            const int qrow = q0 + w16 + g + 8 * rr;
            // scale + mask
            float mx = -1e30f;
#pragma unroll
            for (int jn = 0; jn < 8; jn++) {
                const int col = j0 + jn * 8 + 2 * t;
                float v0 = s[jn][2 * rr + 0] * scale;
                float v1 = s[jn][2 * rr + 1] * scale;
                v0 = (col     <= qrow) ? v0 : -1e30f;
                v1 = (col + 1 <= qrow) ? v1 : -1e30f;
                s[jn][2 * rr + 0] = v0;
                s[jn][2 * rr + 1] = v1;
                mx = fmaxf(mx, fmaxf(v0, v1));
            }
            mx = fmaxf(mx, __shfl_xor_sync(0xffffffffu, mx, 1));
            mx = fmaxf(mx, __shfl_xor_sync(0xffffffffu, mx, 2));
            const float mnew  = fmaxf(m_i[rr], mx);
            const float alpha = __expf(m_i[rr] - mnew);
            float rs = 0.0f;
#pragma unroll
            for (int jn = 0; jn < 8; jn++) {
                const float p0 = __expf(s[jn][2 * rr + 0] - mnew);
                const float p1 = __expf(s[jn][2 * rr + 1] - mnew);
                rs += p0 + p1;
                Ps[(w16 + g + 8 * rr) * QPAD + jn * 8 + 2 * t    ] = f2tf32(p0);
                Ps[(w16 + g + 8 * rr) * QPAD + jn * 8 + 2 * t + 1] = f2tf32(p1);
            }
            rs += __shfl_xor_sync(0xffffffffu, rs, 1);
            rs += __shfl_xor_sync(0xffffffffu, rs, 2);
            l_i[rr] = l_i[rr] * alpha + rs;
            m_i[rr] = mnew;
#pragma unroll
            for (int jn = 0; jn < 8; jn++) {
                o[jn][2 * rr + 0] *= alpha;
                o[jn][2 * rr + 1] *= alpha;
            }
        }
        __syncwarp();

        // ---- O += P @ V  (warp: 16 q rows x 64 d) ----
#pragma unroll
        for (int kc = 0; kc < 64; kc += 8) {
            unsigned a0 = Ps[(w16 + g    ) * QPAD + kc + t];
            unsigned a1 = Ps[(w16 + g + 8) * QPAD + kc + t];
            unsigned a2 = Ps[(w16 + g    ) * QPAD + kc + t + 4];
            unsigned a3 = Ps[(w16 + g + 8) * QPAD + kc + t + 4];
#pragma unroll
            for (int jn = 0; jn < 8; jn++) {
                unsigned b0 = Vs[(kc + t    ) * VPAD + jn * 8 + g];
                unsigned b1 = Vs[(kc + t + 4) * VPAD + jn * 8 + g];
                mma_tf32(o[jn], a0, a1, a2, a3, b0, b1);
            }
        }
    }

    // epilogue: normalize + write y[b][t][h*64 + d]
    const float inv0 = 1.0f / l_i[0];
    const float inv1 = 1.0f / l_i[1];
#pragma unroll
    for (int jn = 0; jn < 8; jn++) {
        const int row = q0 + w16 + g;
        const int d   = h * HD + jn * 8 + 2 * t;
        float2 v0, v1;
        v0.x = o[jn][0] * inv0;
        v0.y = o[jn][1] * inv0;
        v1.x = o[jn][2] * inv1;
        v1.y = o[jn][3] * inv1;
        *(float2*)(y + (size_t)b * TSEQ * CDIM + (size_t)row * CDIM + d)       = v0;
        *(float2*)(y + (size_t)b * TSEQ * CDIM + (size_t)(row + 8) * CDIM + d) = v1;
    }
}

// ---------------------------------------------------------------------------
extern "C" void kernel_launch(void* const* d_in, const int* in_sizes, int n_in,
                              void* d_out, int out_size)
{
    (void)in_sizes; (void)n_in; (void)out_size;
    const float* x      = (const float*)d_in[0];
    const float* w_attn = (const float*)d_in[1];
    const float* b_attn = (const float*)d_in[2];
    const float* w_proj = (const float*)d_in[3];
    const float* b_proj = (const float*)d_in[4];
    float* out = (float*)d_out;

    float* qkv = nullptr;
    float* y   = nullptr;
    cudaGetSymbolAddress((void**)&qkv, g_qkv);
    cudaGetSymbolAddress((void**)&y,   g_y);

    const int M = BATCH * TSEQ;   // 8192

    // 1) QKV projection: [8192,1024] @ [3072,1024]^T + b
    gemm_tf32<<<dim3(3 * CDIM / 128, M / 128), 256>>>(x, w_attn, b_attn, qkv,
                                                      M, 3 * CDIM, CDIM);

    // 2) causal flash attention (tf32 mma)
    const size_t smem = (size_t)(64 * QPAD * 3 + 64 * VPAD) * sizeof(unsigned); // 70656
    cudaFuncSetAttribute(attn_flash_mma, cudaFuncAttributeMaxDynamicSharedMemorySize,
                         (int)smem);
    attn_flash_mma<<<dim3(TSEQ / 64, BATCH * NHEAD), 128, smem>>>(qkv, y);

    // 3) output projection: [8192,1024] @ [1024,1024]^T + b
    gemm_tf32<<<dim3(CDIM / 128, M / 128), 256>>>(y, w_proj, b_proj, out,
                                                  M, CDIM, CDIM);
}